// round 12
// baseline (speedup 1.0000x reference)
#include <cuda_runtime.h>
#include <math.h>

#define LS    32
#define SEQL  1024
#define BSZ   8
#define EMBED 1024
#define KDIM  64
#define NDIM  16
#define VPOW  64
#define RTOT  16384
#define R2    16

typedef unsigned long long ull;

// ---------------- scratch (__device__ globals; no allocation anywhere) -------
__device__ float          g_Apow[4 * VPOW * 1024];   // [a][v][kd*16+n]
__device__ float          g_Bsig[2 * 1024];          // [col][kd*16+n]
__device__ unsigned short g_off16[2 * RTOT * 4];     // [d][r][a] = (a*64+idx)*36
__device__ float          g_coef[2 * RTOT];          // signed: +coef->col0, -coef->col1
__device__ float          g_w[2 * 1024 * 1024];      // [d][p][kd*16+n]
__device__ float          g_Ct[KDIM * 2 * NDIM * 64];// [kd][d][n][h], pre-scaled by 0.25
__device__ float          g_kk[1024 * 4096];         // [p][kd*64+h]
__device__ float          g_ksum[1024 * 1024];       // [p*32+q][e]

// ---------------- f32x2 helpers (FFMA2: 2x fp32 MAC per issue) ---------------
__device__ __forceinline__ ull pk2(float lo, float hi) {
    ull r;
    asm("mov.b64 %0, {%1, %2};" : "=l"(r) : "f"(lo), "f"(hi));
    return r;
}
__device__ __forceinline__ void fma2(ull& d, ull a, ull b) {
    asm("fma.rn.f32x2 %0, %1, %2, %0;" : "+l"(d) : "l"(a), "l"(b));
}
__device__ __forceinline__ float2 upk2(ull v) {
    float2 f;
    asm("mov.b64 {%0, %1}, %2;" : "=f"(f.x), "=f"(f.y) : "l"(v));
    return f;
}

// ---------------- 1. sigmoid + power tables ---------------------------------
__global__ void k_setup(const float* __restrict__ A,
                        const float* __restrict__ B1,
                        const float* __restrict__ B2) {
    int id = blockIdx.x * 256 + threadIdx.x;
    if (id < 4096) {
        float s = 1.f / (1.f + expf(-A[id]));
        int a = id >> 10, t = id & 1023;
        float cur = 1.f;
        #pragma unroll
        for (int v = 0; v < VPOW; v++) {
            g_Apow[(a * VPOW + v) * 1024 + t] = cur;
            cur *= s;
        }
    } else if (id < 4096 + 2048) {
        int j = id - 4096;
        const float* B = (j < 1024) ? B1 : B2;
        g_Bsig[j] = 1.f / (1.f + expf(-B[j & 1023]));
    }
}

// ---------------- 1b. C transpose: Ct[kd][d][n][h] = C_d[(h*64+kd)*16+n]/4 ---
__global__ void k_ct(const float* __restrict__ C1, const float* __restrict__ C2) {
    int id = blockIdx.x * 256 + threadIdx.x;
    int h  = id & 63;
    int n  = (id >> 6) & 15;
    int d  = (id >> 10) & 1;
    int kd = id >> 11;
    const float* C = d ? C2 : C1;
    g_Ct[id] = C[(h * 64 + kd) * 16 + n] * 0.25f;
}

// ---------------- 2. one-hot extraction -> packed smem offsets (stride 36) --
__global__ void k_extract(const float* __restrict__ OM) {
    int gwarp = (blockIdx.x * 256 + threadIdx.x) >> 5;
    int lane  = threadIdx.x & 31;
    int d   = gwarp / (5 * RTOT);
    int rem = gwarp - d * 5 * RTOT;
    int a   = rem / RTOT;
    int r   = rem - a * RTOT;
    int base = ((d * 5 + a) * RTOT + r) * VPOW;
    float v0 = OM[base + lane];
    float v1 = OM[base + 32 + lane];
    unsigned m0 = __ballot_sync(0xffffffffu, v0 != 0.f);
    unsigned m1 = __ballot_sync(0xffffffffu, v1 != 0.f);
    int idx = m0 ? (__ffs(m0) - 1) : (32 + __ffs(m1) - 1);
    if (a < 4) {
        if (lane == 0)
            g_off16[(d * RTOT + r) * 4 + a] = (unsigned short)((a * 64 + idx) * 36);
    } else {
        float val = __shfl_sync(0xffffffffu, (idx < 32) ? v0 : v1, idx & 31);
        if (lane == 0) g_coef[d * RTOT + r] = (idx == 0) ? val : -val;
    }
}

// ---------------- 3. w[d][p][t], LDS.128 gathers, padded rows (no conflicts) -
// grid (32 tc, 8 pc, 2 d), 256 threads.
__global__ void k_w() {
    __shared__ float sA[4 * VPOW * 36];            // 36 KB, row stride 36 floats
    int tc = blockIdx.x, pc = blockIdx.y, d = blockIdx.z;
    int tid = threadIdx.x;
    for (int idx = tid; idx < 8192; idx += 256) {
        int row = idx >> 5, col = idx & 31;
        sA[row * 36 + col] = g_Apow[row * 1024 + tc * 32 + col];
    }
    __syncthreads();

    int warp = tid >> 5, lane = tid & 31;
    int pq = lane >> 3, tq = lane & 7;
    int t4 = tq * 4;
    int tg = tc * 32 + t4;
    float4 b0 = *(const float4*)&g_Bsig[tg];
    float4 b1 = *(const float4*)&g_Bsig[1024 + tg];
    const ushort4* offp = (const ushort4*)g_off16;

    #pragma unroll 1
    for (int pass = 0; pass < 4; pass++) {
        int p = pc * 128 + pass * 32 + warp * 4 + pq;
        int rb = d * RTOT + p * 16;
        float4 acc = make_float4(0.f, 0.f, 0.f, 0.f);
        #pragma unroll
        for (int r2 = 0; r2 < R2; r2++) {
            ushort4 o = offp[rb + r2];
            float  cf = g_coef[rb + r2];
            float4 v0 = *(const float4*)&sA[o.x + t4];
            float4 v1 = *(const float4*)&sA[o.y + t4];
            float4 v2 = *(const float4*)&sA[o.z + t4];
            float4 v3 = *(const float4*)&sA[o.w + t4];
            float s = fabsf(cf);
            float4 bb = (cf > 0.f) ? b0 : b1;
            acc.x = fmaf(v0.x * v1.x * v2.x * v3.x * s, bb.x, acc.x);
            acc.y = fmaf(v0.y * v1.y * v2.y * v3.y * s, bb.y, acc.y);
            acc.z = fmaf(v0.z * v1.z * v2.z * v3.z * s, bb.z, acc.z);
            acc.w = fmaf(v0.w * v1.w * v2.w * v3.w * s, bb.w, acc.w);
        }
        *(float4*)&g_w[(d * 1024 + p) * 1024 + tg] = acc;
    }
}

// ---------------- 4. kk = W x C, smem GEMM -----------------------------------
__global__ void k_kk() {
    __shared__ float Csm[32 * 64];                 // [c][h], c=(d*16+n)
    __shared__ float Wsm[32 * 66];                 // [c][p_l], padded
    int kd = blockIdx.x, pc = blockIdx.y, tid = threadIdx.x;
    int p0 = pc * 64;
    const float* ct = g_Ct + kd * 2048;
    for (int idx = tid; idx < 2048; idx += 256)
        Csm[idx] = ct[idx];
    for (int idx = tid; idx < 2048; idx += 256) {
        int p_l = idx >> 5, c = idx & 31;
        int d = c >> 4, n = c & 15;
        Wsm[c * 66 + p_l] = g_w[(d * 1024 + p0 + p_l) * 1024 + kd * 16 + n];
    }
    __syncthreads();
    int pg = tid >> 3, hg = tid & 7;
    float acc[2][8];
    #pragma unroll
    for (int pi = 0; pi < 2; pi++)
        #pragma unroll
        for (int hi = 0; hi < 8; hi++) acc[pi][hi] = 0.f;
    #pragma unroll
    for (int c = 0; c < 32; c++) {
        float w0 = Wsm[c * 66 + pg * 2];
        float w1 = Wsm[c * 66 + pg * 2 + 1];
        float4 c0 = *(const float4*)&Csm[c * 64 + hg * 8];
        float4 c1 = *(const float4*)&Csm[c * 64 + hg * 8 + 4];
        float cc[8] = {c0.x, c0.y, c0.z, c0.w, c1.x, c1.y, c1.z, c1.w};
        #pragma unroll
        for (int hi = 0; hi < 8; hi++) {
            acc[0][hi] = fmaf(w0, cc[hi], acc[0][hi]);
            acc[1][hi] = fmaf(w1, cc[hi], acc[1][hi]);
        }
    }
    #pragma unroll
    for (int pi = 0; pi < 2; pi++) {
        int p = p0 + pg * 2 + pi;
        float4* dst = (float4*)&g_kk[p * 4096 + kd * 64 + hg * 8];
        dst[0] = make_float4(acc[pi][0], acc[pi][1], acc[pi][2], acc[pi][3]);
        dst[1] = make_float4(acc[pi][4], acc[pi][5], acc[pi][6], acc[pi][7]);
    }
}

// ---------------- 5. direction flips + boundary scaling → ksum[p][e] --------
__device__ __forceinline__ float bfactor(int a, int b) {
    float f = 1.f;
    if (a == 0) f *= 2.f;
    if (b == 0) f *= 2.f;
    if (a == 0 && b == 0) f *= 0.25f;
    return f;
}

__global__ void k_ksum() {
    __shared__ float sh[4][1024];
    int pi = blockIdx.x, pj = blockIdx.y, tid = threadIdx.x;
    int rows[4] = { pi * 32 + pj, (31 - pi) * 32 + pj,
                    pi * 32 + (31 - pj), (31 - pi) * 32 + (31 - pj) };
    #pragma unroll
    for (int dir = 0; dir < 4; dir++)
        for (int idx = tid; idx < 1024; idx += 256)
            sh[dir][idx] = g_kk[rows[dir] * 4096 + dir * 1024 + idx];
    __syncthreads();
    float f0 = bfactor(pi, pj), f1 = bfactor(31 - pi, pj);
    float f2 = bfactor(pi, 31 - pj), f3 = bfactor(31 - pi, 31 - pj);
    for (int e = tid; e < 1024; e += 256) {
        int h = e >> 4, s = e & 15;
        int o = s * 64 + h;
        float v = f0 * sh[0][o] + f1 * sh[1][o] + f2 * sh[2][o] + f3 * sh[3][o];
        g_ksum[(pi * 32 + pj) * 1024 + e] = v;
    }
}

// ---------------- 6. triangular conv: i-PAIR per block, batch-pair f32x2 -----
// grid (8 ec, 16 pair, 4 bp), 128 threads. Block computes output rows i0 and
// i0+1 sharing every x-row load (x traffic and load-latency per FMA halved).
// Regs: accA+accB 128 + xm 32 + k 32 ≈ 210 -> launch_bounds(128,2), 8 warps/SM.
__global__ void __launch_bounds__(128, 2)
k_conv(const float* __restrict__ x, const float* __restrict__ omega,
       float* __restrict__ out) {
    int e  = blockIdx.x * 128 + threadIdx.x;
    int i0 = 30 - 2 * (int)blockIdx.y;             // pair (i0, i0+1), heavy first
    int b0 = blockIdx.z * 2;

    ull accA[32], accB[32];                        // A = row i0+1, B = row i0
    #pragma unroll
    for (int j = 0; j < 32; j++) { accA[j] = 0ull; accB[j] = 0ull; }

    const float* xa = x + b0 * 1024 + e;                        // x grid-row u
    const float* kA = g_ksum + (size_t)((i0 + 1) * 32) * 1024 + e; // row i0+1-u
    const float* kB = g_ksum + (size_t)(i0 * 32) * 1024 + e;       // row i0-u

    #pragma unroll 1
    for (int u = 0; u <= i0; u++) {
        #pragma unroll
        for (int mc = 0; mc < 2; mc++) {
            ull xm[16];
            #pragma unroll
            for (int t = 0; t < 16; t++) {
                const float* xp = xa + (mc * 16 + t) * 8192;
                xm[t] = pk2(xp[0], xp[1024]);
            }
            #pragma unroll
            for (int qc = 0; qc < 4; qc++) {
                ull a2[8], b2[8];
                #pragma unroll
                for (int t = 0; t < 8; t++) {
                    float va = kA[(qc * 8 + t) * 1024];
                    float vb = kB[(qc * 8 + t) * 1024];
                    a2[t] = pk2(va, va);
                    b2[t] = pk2(vb, vb);
                }
                #pragma unroll
                for (int m = 0; m < 16; m++) {
                    #pragma unroll
                    for (int q = 0; q < 8; q++) {
                        int j = mc * 16 + m + qc * 8 + q;      // compile-time
                        if (j < 32) {
                            fma2(accA[j], a2[q], xm[m]);
                            fma2(accB[j], b2[q], xm[m]);
                        }
                    }
                }
            }
        }
        xa += 32 * 8192;
        kA -= 32 * 1024;
        kB -= 32 * 1024;
    }

    // epilogue u = i0+1: row A only, kA now points at kernel grid-row 0
    #pragma unroll
    for (int mc = 0; mc < 2; mc++) {
        ull xm[16];
        #pragma unroll
        for (int t = 0; t < 16; t++) {
            const float* xp = xa + (mc * 16 + t) * 8192;
            xm[t] = pk2(xp[0], xp[1024]);
        }
        #pragma unroll
        for (int qc = 0; qc < 4; qc++) {
            ull a2[8];
            #pragma unroll
            for (int t = 0; t < 8; t++) {
                float va = kA[(qc * 8 + t) * 1024];
                a2[t] = pk2(va, va);
            }
            #pragma unroll
            for (int m = 0; m < 16; m++) {
                #pragma unroll
                for (int q = 0; q < 8; q++) {
                    int j = mc * 16 + m + qc * 8 + q;
                    if (j < 32) fma2(accA[j], a2[q], xm[m]);
                }
            }
        }
    }

    // fused residual + store (x rows hot in L1/L2)
    float om = omega[e];
    ull omp = pk2(om, om);
    const float* xA = xa;                                          // row i0+1
    const float* xB = x + (size_t)((i0 * 32) * 8 + b0) * 1024 + e; // row i0
    float* oA = out + (size_t)(((i0 + 1) * 32) * 8 + b0) * 1024 + e;
    float* oB = out + (size_t)((i0 * 32) * 8 + b0) * 1024 + e;
    #pragma unroll
    for (int j = 0; j < 32; j++) {
        ull xvA = pk2(xA[j * 8192], xA[j * 8192 + 1024]);
        fma2(accA[j], omp, xvA);
        float2 vA = upk2(accA[j]);
        oA[j * 8192]        = vA.x;
        oA[j * 8192 + 1024] = vA.y;
        ull xvB = pk2(xB[j * 8192], xB[j * 8192 + 1024]);
        fma2(accB[j], omp, xvB);
        float2 vB = upk2(accB[j]);
        oB[j * 8192]        = vB.x;
        oB[j * 8192 + 1024] = vB.y;
    }
}

// ---------------- launch -----------------------------------------------------
extern "C" void kernel_launch(void* const* d_in, const int* in_sizes, int n_in,
                              void* d_out, int out_size) {
    const float* x   = (const float*)d_in[0];
    const float* A   = (const float*)d_in[1];
    const float* B1  = (const float*)d_in[2];
    const float* B2  = (const float*)d_in[3];
    const float* C1  = (const float*)d_in[4];
    const float* C2  = (const float*)d_in[5];
    const float* om  = (const float*)d_in[6];
    const float* OM  = (const float*)d_in[7];
    float* out = (float*)d_out;

    k_setup<<<24, 256>>>(A, B1, B2);
    k_ct<<<512, 256>>>(C1, C2);
    k_extract<<<(2 * 5 * RTOT) / 8, 256>>>(OM);
    k_w<<<dim3(32, 8, 2), 256>>>();
    k_kk<<<dim3(64, 16), 256>>>();
    k_ksum<<<dim3(32, 32), 256>>>();
    k_conv<<<dim3(8, 16, 4), 128>>>(x, om, out);
}

// round 13
// speedup vs baseline: 1.0888x; 1.0888x over previous
#include <cuda_runtime.h>
#include <math.h>

#define LS    32
#define SEQL  1024
#define BSZ   8
#define EMBED 1024
#define KDIM  64
#define NDIM  16
#define VPOW  64
#define RTOT  16384
#define R2    16

typedef unsigned long long ull;

// ---------------- scratch (__device__ globals; no allocation anywhere) -------
__device__ float          g_Apow[4 * VPOW * 1024];   // [a][v][kd*16+n]
__device__ float          g_Bsig[2 * 1024];          // [col][kd*16+n]
__device__ unsigned short g_off16[2 * RTOT * 4];     // [d][r][a] = (a*64+idx)*32
__device__ float          g_coef[2 * RTOT];          // signed: +coef->col0, -coef->col1
__device__ float          g_w[2 * 1024 * 1024];      // [d][p][kd*16+n]
__device__ float          g_Ct[KDIM * 2 * NDIM * 64];// [kd][d][n][h], pre-scaled by 0.25
__device__ float          g_kk[1024 * 4096];         // [p][kd*64+h]
__device__ float          g_ksum[1024 * 1024];       // [p*32+q][e]

// ---------------- f32x2 helpers (FFMA2: 2x fp32 MAC per issue) ---------------
__device__ __forceinline__ void fma2(ull& d, ull a, ull b) {
    asm("fma.rn.f32x2 %0, %1, %2, %0;" : "+l"(d) : "l"(a), "l"(b));
}

// ---------------- 1. sigmoid + power tables ---------------------------------
__global__ void k_setup(const float* __restrict__ A,
                        const float* __restrict__ B1,
                        const float* __restrict__ B2) {
    int id = blockIdx.x * 256 + threadIdx.x;
    if (id < 4096) {
        float s = 1.f / (1.f + expf(-A[id]));
        int a = id >> 10, t = id & 1023;
        float cur = 1.f;
        #pragma unroll
        for (int v = 0; v < VPOW; v++) {
            g_Apow[(a * VPOW + v) * 1024 + t] = cur;
            cur *= s;
        }
    } else if (id < 4096 + 2048) {
        int j = id - 4096;
        const float* B = (j < 1024) ? B1 : B2;
        g_Bsig[j] = 1.f / (1.f + expf(-B[j & 1023]));
    }
}

// ---------------- 1b. C transpose: Ct[kd][d][n][h] = C_d[(h*64+kd)*16+n]/4 ---
__global__ void k_ct(const float* __restrict__ C1, const float* __restrict__ C2) {
    int id = blockIdx.x * 256 + threadIdx.x;
    int h  = id & 63;
    int n  = (id >> 6) & 15;
    int d  = (id >> 10) & 1;
    int kd = id >> 11;
    const float* C = d ? C2 : C1;
    g_Ct[id] = C[(h * 64 + kd) * 16 + n] * 0.25f;
}

// ---------------- 2. one-hot extraction -> packed smem offsets --------------
__global__ void k_extract(const float* __restrict__ OM) {
    int gwarp = (blockIdx.x * 256 + threadIdx.x) >> 5;
    int lane  = threadIdx.x & 31;
    int d   = gwarp / (5 * RTOT);
    int rem = gwarp - d * 5 * RTOT;
    int a   = rem / RTOT;
    int r   = rem - a * RTOT;
    int base = ((d * 5 + a) * RTOT + r) * VPOW;
    float v0 = OM[base + lane];
    float v1 = OM[base + 32 + lane];
    unsigned m0 = __ballot_sync(0xffffffffu, v0 != 0.f);
    unsigned m1 = __ballot_sync(0xffffffffu, v1 != 0.f);
    int idx = m0 ? (__ffs(m0) - 1) : (32 + __ffs(m1) - 1);
    if (a < 4) {
        if (lane == 0)
            g_off16[(d * RTOT + r) * 4 + a] = (unsigned short)((a * 64 + idx) * 32);
    } else {
        float val = __shfl_sync(0xffffffffu, (idx < 32) ? v0 : v1, idx & 31);
        if (lane == 0) g_coef[d * RTOT + r] = (idx == 0) ? val : -val;
    }
}

// ---------------- 3. w[d][p][t], LDS.128 gathers, 1024 blocks ----------------
// grid (32 tc, 16 pc, 2 d), 256 threads, 2 passes each -> 6.9 blocks/SM.
__global__ void k_w() {
    __shared__ float sA[4 * VPOW * 32];            // 32 KB Apow slice for t-chunk
    int tc = blockIdx.x, pc = blockIdx.y, d = blockIdx.z;
    int tid = threadIdx.x;
    for (int idx = tid; idx < 8192; idx += 256)
        sA[idx] = g_Apow[(idx >> 5) * 1024 + tc * 32 + (idx & 31)];
    __syncthreads();

    int warp = tid >> 5, lane = tid & 31;
    int pq = lane >> 3, tq = lane & 7;
    int t4 = tq * 4;
    int tg = tc * 32 + t4;
    float4 b0 = *(const float4*)&g_Bsig[tg];
    float4 b1 = *(const float4*)&g_Bsig[1024 + tg];
    const ushort4* offp = (const ushort4*)g_off16;

    #pragma unroll 1
    for (int pass = 0; pass < 2; pass++) {
        int p = pc * 64 + pass * 32 + warp * 4 + pq;
        int rb = d * RTOT + p * 16;
        float4 acc = make_float4(0.f, 0.f, 0.f, 0.f);
        #pragma unroll
        for (int r2 = 0; r2 < R2; r2++) {
            ushort4 o = offp[rb + r2];
            float  cf = g_coef[rb + r2];
            float4 v0 = *(const float4*)&sA[o.x + t4];
            float4 v1 = *(const float4*)&sA[o.y + t4];
            float4 v2 = *(const float4*)&sA[o.z + t4];
            float4 v3 = *(const float4*)&sA[o.w + t4];
            float s = fabsf(cf);
            float4 bb = (cf > 0.f) ? b0 : b1;
            acc.x = fmaf(v0.x * v1.x * v2.x * v3.x * s, bb.x, acc.x);
            acc.y = fmaf(v0.y * v1.y * v2.y * v3.y * s, bb.y, acc.y);
            acc.z = fmaf(v0.z * v1.z * v2.z * v3.z * s, bb.z, acc.z);
            acc.w = fmaf(v0.w * v1.w * v2.w * v3.w * s, bb.w, acc.w);
        }
        *(float4*)&g_w[(d * 1024 + p) * 1024 + tg] = acc;
    }
}

// ---------------- 4. kk = W x C, smem GEMM -----------------------------------
__global__ void k_kk() {
    __shared__ float Csm[32 * 64];                 // [c][h], c=(d*16+n)
    __shared__ float Wsm[32 * 66];                 // [c][p_l], padded
    int kd = blockIdx.x, pc = blockIdx.y, tid = threadIdx.x;
    int p0 = pc * 64;
    const float* ct = g_Ct + kd * 2048;
    for (int idx = tid; idx < 2048; idx += 256)
        Csm[idx] = ct[idx];
    for (int idx = tid; idx < 2048; idx += 256) {
        int p_l = idx >> 5, c = idx & 31;
        int d = c >> 4, n = c & 15;
        Wsm[c * 66 + p_l] = g_w[(d * 1024 + p0 + p_l) * 1024 + kd * 16 + n];
    }
    __syncthreads();
    int pg = tid >> 3, hg = tid & 7;
    float acc[2][8];
    #pragma unroll
    for (int pi = 0; pi < 2; pi++)
        #pragma unroll
        for (int hi = 0; hi < 8; hi++) acc[pi][hi] = 0.f;
    #pragma unroll
    for (int c = 0; c < 32; c++) {
        float w0 = Wsm[c * 66 + pg * 2];
        float w1 = Wsm[c * 66 + pg * 2 + 1];
        float4 c0 = *(const float4*)&Csm[c * 64 + hg * 8];
        float4 c1 = *(const float4*)&Csm[c * 64 + hg * 8 + 4];
        float cc[8] = {c0.x, c0.y, c0.z, c0.w, c1.x, c1.y, c1.z, c1.w};
        #pragma unroll
        for (int hi = 0; hi < 8; hi++) {
            acc[0][hi] = fmaf(w0, cc[hi], acc[0][hi]);
            acc[1][hi] = fmaf(w1, cc[hi], acc[1][hi]);
        }
    }
    #pragma unroll
    for (int pi = 0; pi < 2; pi++) {
        int p = p0 + pg * 2 + pi;
        float4* dst = (float4*)&g_kk[p * 4096 + kd * 64 + hg * 8];
        dst[0] = make_float4(acc[pi][0], acc[pi][1], acc[pi][2], acc[pi][3]);
        dst[1] = make_float4(acc[pi][4], acc[pi][5], acc[pi][6], acc[pi][7]);
    }
}

// ---------------- 5. direction flips + boundary scaling → ksum[p][e] --------
__device__ __forceinline__ float bfactor(int a, int b) {
    float f = 1.f;
    if (a == 0) f *= 2.f;
    if (b == 0) f *= 2.f;
    if (a == 0 && b == 0) f *= 0.25f;
    return f;
}

__global__ void k_ksum() {
    __shared__ float sh[4][1024];
    int pi = blockIdx.x, pj = blockIdx.y, tid = threadIdx.x;
    int rows[4] = { pi * 32 + pj, (31 - pi) * 32 + pj,
                    pi * 32 + (31 - pj), (31 - pi) * 32 + (31 - pj) };
    #pragma unroll
    for (int dir = 0; dir < 4; dir++)
        for (int idx = tid; idx < 1024; idx += 256)
            sh[dir][idx] = g_kk[rows[dir] * 4096 + dir * 1024 + idx];
    __syncthreads();
    float f0 = bfactor(pi, pj), f1 = bfactor(31 - pi, pj);
    float f2 = bfactor(pi, 31 - pj), f3 = bfactor(31 - pi, 31 - pj);
    for (int e = tid; e < 1024; e += 256) {
        int h = e >> 4, s = e & 15;
        int o = s * 64 + h;
        float v = f0 * sh[0][o] + f1 * sh[1][o] + f2 * sh[2][o] + f3 * sh[3][o];
        g_ksum[(pi * 32 + pj) * 1024 + e] = v;
    }
}

// ---------------- 6. triangular conv, e-PAIR f32x2: all 64-bit LDG/STG -------
// grid (4 ec, 32 i [heavy first], 8 b), 128 threads. Thread owns e-pair
// (e0, e0+1): x, k, omega, out all load/store natively as f32x2 (no packing).
// Regs: acc 64 + xr 64 + k2 16 + addr ~ 156 -> 3 blocks/SM, 12 warps.
__global__ void __launch_bounds__(128, 3)
k_conv(const float* __restrict__ x, const float* __restrict__ omega,
       float* __restrict__ out) {
    int e0 = blockIdx.x * 256 + threadIdx.x * 2;
    int i  = 31 - (int)blockIdx.y;                 // heavy blocks launch first
    int b  = blockIdx.z;

    ull acc[32];
    #pragma unroll
    for (int j = 0; j < 32; j++) acc[j] = 0ull;
    ull xr[32];

    const float* xa = x + b * 1024 + e0;           // advances one grid-row per u
    const float* ka = g_ksum + (size_t)(i * 32) * 1024 + e0; // retreats per u

    #pragma unroll 1
    for (int u = 0; u <= i; u++) {
        #pragma unroll
        for (int j = 0; j < 32; j++)
            xr[j] = *(const ull*)(xa + j * 8192); // LDG.64 e-pair
        #pragma unroll
        for (int qc = 0; qc < 4; qc++) {
            ull k2[8];
            #pragma unroll
            for (int t = 0; t < 8; t++)
                k2[t] = *(const ull*)(ka + (qc * 8 + t) * 1024); // LDG.64 e-pair
            #pragma unroll
            for (int j = qc * 8; j < 32; j++) {
                int qmax = (j < qc * 8 + 7) ? j : (qc * 8 + 7);
                #pragma unroll
                for (int q = qc * 8; q <= qmax; q++)
                    fma2(acc[j], k2[q - qc * 8], xr[j - q]);
            }
        }
        xa += 32 * 8192;
        ka -= 32 * 1024;
    }

    // xr holds x grid-row i (last u) -> fused residual, native 64-bit stores
    ull omp = *(const ull*)(omega + e0);
    float* oa = out + (size_t)((i * 32) * 8 + b) * 1024 + e0;
    #pragma unroll
    for (int j = 0; j < 32; j++) {
        fma2(acc[j], omp, xr[j]);
        *(ull*)(oa + j * 8192) = acc[j];
    }
}

// ---------------- launch -----------------------------------------------------
extern "C" void kernel_launch(void* const* d_in, const int* in_sizes, int n_in,
                              void* d_out, int out_size) {
    const float* x   = (const float*)d_in[0];
    const float* A   = (const float*)d_in[1];
    const float* B1  = (const float*)d_in[2];
    const float* B2  = (const float*)d_in[3];
    const float* C1  = (const float*)d_in[4];
    const float* C2  = (const float*)d_in[5];
    const float* om  = (const float*)d_in[6];
    const float* OM  = (const float*)d_in[7];
    float* out = (float*)d_out;

    k_setup<<<24, 256>>>(A, B1, B2);
    k_ct<<<512, 256>>>(C1, C2);
    k_extract<<<(2 * 5 * RTOT) / 8, 256>>>(OM);
    k_w<<<dim3(32, 16, 2), 256>>>();
    k_kk<<<dim3(64, 16), 256>>>();
    k_ksum<<<dim3(32, 32), 256>>>();
    k_conv<<<dim3(4, 32, 8), 128>>>(x, om, out);
}

// round 14
// speedup vs baseline: 1.1973x; 1.0997x over previous
#include <cuda_runtime.h>
#include <math.h>

#define LS    32
#define SEQL  1024
#define BSZ   8
#define EMBED 1024
#define KDIM  64
#define NDIM  16
#define VPOW  64
#define RTOT  16384
#define R2    16

typedef unsigned long long ull;

// ---------------- scratch (__device__ globals; no allocation anywhere) -------
__device__ float          g_Apow[4 * VPOW * 1024];   // [a][v][kd*16+n]
__device__ float          g_Bsig[2 * 1024];          // [col][kd*16+n]
__device__ unsigned short g_off16[2 * RTOT * 4];     // [d][r][a] = (a*64+idx)*32
__device__ float          g_coef[2 * RTOT];          // signed: +coef->col0, -coef->col1
__device__ float          g_w[2 * 1024 * 1024];      // [d][p][kd*16+n]
__device__ float          g_Ct[KDIM * 2 * NDIM * 64];// [kd][d][n][h], pre-scaled by 0.25
__device__ float          g_kk[1024 * 4096];         // [p][kd*64+h]
__device__ float          g_ksum[1024 * 1024];       // [p*32+q][e]

// ---------------- f32x2 helpers ----------------------------------------------
__device__ __forceinline__ ull pk2(float lo, float hi) {
    ull r;
    asm("mov.b64 %0, {%1, %2};" : "=l"(r) : "f"(lo), "f"(hi));
    return r;
}
__device__ __forceinline__ void fma2(ull& d, ull a, ull b) {
    asm("fma.rn.f32x2 %0, %1, %2, %0;" : "+l"(d) : "l"(a), "l"(b));
}
__device__ __forceinline__ float2 upk2(ull v) {
    float2 f;
    asm("mov.b64 {%0, %1}, %2;" : "=f"(f.x), "=f"(f.y) : "l"(v));
    return f;
}

// ---------------- 1. merged init: extract | setup | ct -----------------------
// blocks [0, 20480): extract (8 warps each, 163840 warps total)
// blocks [20480, 20992): ct (131072 ids)
// blocks [20992, 21016): setup (6144 ids)
#define NB_EXTRACT 20480
#define NB_CT      512
#define NB_SETUP   24

__global__ void k_init(const float* __restrict__ A,
                       const float* __restrict__ B1,
                       const float* __restrict__ B2,
                       const float* __restrict__ C1,
                       const float* __restrict__ C2,
                       const float* __restrict__ OM) {
    int blk = blockIdx.x;
    if (blk < NB_EXTRACT) {
        int gwarp = (blk * 256 + threadIdx.x) >> 5;
        int lane  = threadIdx.x & 31;
        int d   = gwarp / (5 * RTOT);
        int rem = gwarp - d * 5 * RTOT;
        int a   = rem / RTOT;
        int r   = rem - a * RTOT;
        int base = ((d * 5 + a) * RTOT + r) * VPOW;
        float v0 = OM[base + lane];
        float v1 = OM[base + 32 + lane];
        unsigned m0 = __ballot_sync(0xffffffffu, v0 != 0.f);
        unsigned m1 = __ballot_sync(0xffffffffu, v1 != 0.f);
        int idx = m0 ? (__ffs(m0) - 1) : (32 + __ffs(m1) - 1);
        if (a < 4) {
            if (lane == 0)
                g_off16[(d * RTOT + r) * 4 + a] = (unsigned short)((a * 64 + idx) * 32);
        } else {
            float val = __shfl_sync(0xffffffffu, (idx < 32) ? v0 : v1, idx & 31);
            if (lane == 0) g_coef[d * RTOT + r] = (idx == 0) ? val : -val;
        }
    } else if (blk < NB_EXTRACT + NB_CT) {
        int id = (blk - NB_EXTRACT) * 256 + threadIdx.x;   // 131072
        int h  = id & 63;
        int n  = (id >> 6) & 15;
        int d  = (id >> 10) & 1;
        int kd = id >> 11;
        const float* C = d ? C2 : C1;
        g_Ct[id] = C[(h * 64 + kd) * 16 + n] * 0.25f;
    } else {
        int id = (blk - NB_EXTRACT - NB_CT) * 256 + threadIdx.x;
        if (id < 4096) {
            float s = 1.f / (1.f + expf(-A[id]));
            int a = id >> 10, t = id & 1023;
            float cur = 1.f;
            #pragma unroll
            for (int v = 0; v < VPOW; v++) {
                g_Apow[(a * VPOW + v) * 1024 + t] = cur;
                cur *= s;
            }
        } else if (id < 4096 + 2048) {
            int j = id - 4096;
            const float* B = (j < 1024) ? B1 : B2;
            g_Bsig[j] = 1.f / (1.f + expf(-B[j & 1023]));
        }
    }
}

// ---------------- 3. w[d][p][t], LDS.128 gathers, 1024 blocks ----------------
// grid (32 tc, 16 pc, 2 d), 256 threads, 2 passes each.
__global__ void k_w() {
    __shared__ float sA[4 * VPOW * 32];            // 32 KB Apow slice for t-chunk
    int tc = blockIdx.x, pc = blockIdx.y, d = blockIdx.z;
    int tid = threadIdx.x;
    for (int idx = tid; idx < 8192; idx += 256)
        sA[idx] = g_Apow[(idx >> 5) * 1024 + tc * 32 + (idx & 31)];
    __syncthreads();

    int warp = tid >> 5, lane = tid & 31;
    int pq = lane >> 3, tq = lane & 7;
    int t4 = tq * 4;
    int tg = tc * 32 + t4;
    float4 b0 = *(const float4*)&g_Bsig[tg];
    float4 b1 = *(const float4*)&g_Bsig[1024 + tg];
    const ushort4* offp = (const ushort4*)g_off16;

    #pragma unroll 1
    for (int pass = 0; pass < 2; pass++) {
        int p = pc * 64 + pass * 32 + warp * 4 + pq;
        int rb = d * RTOT + p * 16;
        float4 acc = make_float4(0.f, 0.f, 0.f, 0.f);
        #pragma unroll
        for (int r2 = 0; r2 < R2; r2++) {
            ushort4 o = offp[rb + r2];
            float  cf = g_coef[rb + r2];
            float4 v0 = *(const float4*)&sA[o.x + t4];
            float4 v1 = *(const float4*)&sA[o.y + t4];
            float4 v2 = *(const float4*)&sA[o.z + t4];
            float4 v3 = *(const float4*)&sA[o.w + t4];
            float s = fabsf(cf);
            float4 bb = (cf > 0.f) ? b0 : b1;
            acc.x = fmaf(v0.x * v1.x * v2.x * v3.x * s, bb.x, acc.x);
            acc.y = fmaf(v0.y * v1.y * v2.y * v3.y * s, bb.y, acc.y);
            acc.z = fmaf(v0.z * v1.z * v2.z * v3.z * s, bb.z, acc.z);
            acc.w = fmaf(v0.w * v1.w * v2.w * v3.w * s, bb.w, acc.w);
        }
        *(float4*)&g_w[(d * 1024 + p) * 1024 + tg] = acc;
    }
}

// ---------------- 4. kk = W x C, smem GEMM -----------------------------------
__global__ void k_kk() {
    __shared__ float Csm[32 * 64];                 // [c][h], c=(d*16+n)
    __shared__ float Wsm[32 * 66];                 // [c][p_l], padded
    int kd = blockIdx.x, pc = blockIdx.y, tid = threadIdx.x;
    int p0 = pc * 64;
    const float* ct = g_Ct + kd * 2048;
    for (int idx = tid; idx < 2048; idx += 256)
        Csm[idx] = ct[idx];
    for (int idx = tid; idx < 2048; idx += 256) {
        int p_l = idx >> 5, c = idx & 31;
        int d = c >> 4, n = c & 15;
        Wsm[c * 66 + p_l] = g_w[(d * 1024 + p0 + p_l) * 1024 + kd * 16 + n];
    }
    __syncthreads();
    int pg = tid >> 3, hg = tid & 7;
    float acc[2][8];
    #pragma unroll
    for (int pi = 0; pi < 2; pi++)
        #pragma unroll
        for (int hi = 0; hi < 8; hi++) acc[pi][hi] = 0.f;
    #pragma unroll
    for (int c = 0; c < 32; c++) {
        float w0 = Wsm[c * 66 + pg * 2];
        float w1 = Wsm[c * 66 + pg * 2 + 1];
        float4 c0 = *(const float4*)&Csm[c * 64 + hg * 8];
        float4 c1 = *(const float4*)&Csm[c * 64 + hg * 8 + 4];
        float cc[8] = {c0.x, c0.y, c0.z, c0.w, c1.x, c1.y, c1.z, c1.w};
        #pragma unroll
        for (int hi = 0; hi < 8; hi++) {
            acc[0][hi] = fmaf(w0, cc[hi], acc[0][hi]);
            acc[1][hi] = fmaf(w1, cc[hi], acc[1][hi]);
        }
    }
    #pragma unroll
    for (int pi = 0; pi < 2; pi++) {
        int p = p0 + pg * 2 + pi;
        float4* dst = (float4*)&g_kk[p * 4096 + kd * 64 + hg * 8];
        dst[0] = make_float4(acc[pi][0], acc[pi][1], acc[pi][2], acc[pi][3]);
        dst[1] = make_float4(acc[pi][4], acc[pi][5], acc[pi][6], acc[pi][7]);
    }
}

// ---------------- 5. direction flips + boundary scaling → ksum[p][e] --------
__device__ __forceinline__ float bfactor(int a, int b) {
    float f = 1.f;
    if (a == 0) f *= 2.f;
    if (b == 0) f *= 2.f;
    if (a == 0 && b == 0) f *= 0.25f;
    return f;
}

__global__ void k_ksum() {
    __shared__ float sh[4][1024];
    int pi = blockIdx.x, pj = blockIdx.y, tid = threadIdx.x;
    int rows[4] = { pi * 32 + pj, (31 - pi) * 32 + pj,
                    pi * 32 + (31 - pj), (31 - pi) * 32 + (31 - pj) };
    #pragma unroll
    for (int dir = 0; dir < 4; dir++)
        for (int idx = tid; idx < 1024; idx += 256)
            sh[dir][idx] = g_kk[rows[dir] * 4096 + dir * 1024 + idx];
    __syncthreads();
    float f0 = bfactor(pi, pj), f1 = bfactor(31 - pi, pj);
    float f2 = bfactor(pi, 31 - pj), f3 = bfactor(31 - pi, 31 - pj);
    for (int e = tid; e < 1024; e += 256) {
        int h = e >> 4, s = e & 15;
        int o = s * 64 + h;
        float v = f0 * sh[0][o] + f1 * sh[1][o] + f2 * sh[2][o] + f3 * sh[3][o];
        g_ksum[(pi * 32 + pj) * 1024 + e] = v;
    }
}

// ---------------- 6. triangular conv (R8 measured-best, verbatim) ------------
// grid (8 e-chunks, 32 i [heavy first], 4 batch-pairs), 128 threads.
__global__ void __launch_bounds__(128, 3)
k_conv(const float* __restrict__ x, const float* __restrict__ omega,
       float* __restrict__ out) {
    int e  = blockIdx.x * 128 + threadIdx.x;
    int i  = 31 - (int)blockIdx.y;                 // heavy blocks launch first
    int b0 = blockIdx.z * 2;

    ull acc[32];                                   // lanes = (b0, b0+1)
    #pragma unroll
    for (int j = 0; j < 32; j++) acc[j] = 0ull;
    ull xr[32];

    const float* xa = x + b0 * 1024 + e;           // advances one grid-row per u
    const float* ka = g_ksum + (size_t)(i * 32) * 1024 + e;

    #pragma unroll 1
    for (int u = 0; u <= i; u++) {
        #pragma unroll
        for (int j = 0; j < 32; j++)
            xr[j] = pk2(xa[j * 8192], xa[j * 8192 + 1024]);
        #pragma unroll
        for (int qc = 0; qc < 4; qc++) {
            ull k2[8];
            #pragma unroll
            for (int t = 0; t < 8; t++) {
                float kv = ka[(qc * 8 + t) * 1024];
                k2[t] = pk2(kv, kv);
            }
            #pragma unroll
            for (int j = qc * 8; j < 32; j++) {
                int qmax = (j < qc * 8 + 7) ? j : (qc * 8 + 7);
                #pragma unroll
                for (int q = qc * 8; q <= qmax; q++)
                    fma2(acc[j], k2[q - qc * 8], xr[j - q]);
            }
        }
        xa += 32 * 8192;
        ka -= 32 * 1024;
    }

    // xr holds x grid-row i (last u) -> fused residual
    float om = omega[e];
    ull omp = pk2(om, om);
    float* oa = out + (size_t)((i * 32) * 8 + b0) * 1024 + e;
    #pragma unroll
    for (int j = 0; j < 32; j++) {
        fma2(acc[j], omp, xr[j]);
        float2 v = upk2(acc[j]);
        oa[j * 8192]        = v.x;
        oa[j * 8192 + 1024] = v.y;
    }
}

// ---------------- launch -----------------------------------------------------
extern "C" void kernel_launch(void* const* d_in, const int* in_sizes, int n_in,
                              void* d_out, int out_size) {
    const float* x   = (const float*)d_in[0];
    const float* A   = (const float*)d_in[1];
    const float* B1  = (const float*)d_in[2];
    const float* B2  = (const float*)d_in[3];
    const float* C1  = (const float*)d_in[4];
    const float* C2  = (const float*)d_in[5];
    const float* om  = (const float*)d_in[6];
    const float* OM  = (const float*)d_in[7];
    float* out = (float*)d_out;

    k_init<<<NB_EXTRACT + NB_CT + NB_SETUP, 256>>>(A, B1, B2, C1, C2, OM);
    k_w<<<dim3(32, 16, 2), 256>>>();
    k_kk<<<dim3(64, 16), 256>>>();
    k_ksum<<<dim3(32, 32), 256>>>();
    k_conv<<<dim3(8, 32, 4), 128>>>(x, om, out);
}

// round 15
// speedup vs baseline: 1.2386x; 1.0344x over previous
#include <cuda_runtime.h>
#include <math.h>

#define LS    32
#define SEQL  1024
#define BSZ   8
#define EMBED 1024
#define KDIM  64
#define NDIM  16
#define VPOW  64
#define RTOT  16384
#define R2    16

typedef unsigned long long ull;

// ---------------- scratch (__device__ globals; no allocation anywhere) -------
__device__ float          g_Apow[4 * VPOW * 1024];   // [a][v][kd*16+n]
__device__ float          g_Bsig[2 * 1024];          // [col][kd*16+n]
__device__ unsigned short g_off16[2 * RTOT * 4];     // [d][r][a] = (a*64+idx)*32
__device__ float          g_coef[2 * RTOT];          // signed: +coef->col0, -coef->col1
__device__ float          g_w[2 * 1024 * 1024];      // [d][p][kd*16+n]
__device__ float          g_Ct[KDIM * 2 * NDIM * 64];// [kd][d][n][h], pre-scaled by 0.25
__device__ float          g_kk[1024 * 4096];         // [p][kd*64+h]
__device__ float          g_ksum[1024 * 1024];       // [p*32+q][e]

// ---------------- f32x2 helpers ----------------------------------------------
__device__ __forceinline__ ull pk2(float lo, float hi) {
    ull r;
    asm("mov.b64 %0, {%1, %2};" : "=l"(r) : "f"(lo), "f"(hi));
    return r;
}
__device__ __forceinline__ void fma2(ull& d, ull a, ull b) {
    asm("fma.rn.f32x2 %0, %1, %2, %0;" : "+l"(d) : "l"(a), "l"(b));
}
__device__ __forceinline__ float2 upk2(ull v) {
    float2 f;
    asm("mov.b64 {%0, %1}, %2;" : "=f"(f.x), "=f"(f.y) : "l"(v));
    return f;
}

// ---------------- 1. merged init: extract | setup | ct -----------------------
#define NB_EXTRACT 20480
#define NB_CT      512
#define NB_SETUP   24

__global__ void k_init(const float* __restrict__ A,
                       const float* __restrict__ B1,
                       const float* __restrict__ B2,
                       const float* __restrict__ C1,
                       const float* __restrict__ C2,
                       const float* __restrict__ OM) {
    int blk = blockIdx.x;
    if (blk < NB_EXTRACT) {
        int gwarp = (blk * 256 + threadIdx.x) >> 5;
        int lane  = threadIdx.x & 31;
        int d   = gwarp / (5 * RTOT);
        int rem = gwarp - d * 5 * RTOT;
        int a   = rem / RTOT;
        int r   = rem - a * RTOT;
        int base = ((d * 5 + a) * RTOT + r) * VPOW;
        float v0 = OM[base + lane];
        float v1 = OM[base + 32 + lane];
        unsigned m0 = __ballot_sync(0xffffffffu, v0 != 0.f);
        unsigned m1 = __ballot_sync(0xffffffffu, v1 != 0.f);
        int idx = m0 ? (__ffs(m0) - 1) : (32 + __ffs(m1) - 1);
        if (a < 4) {
            if (lane == 0)
                g_off16[(d * RTOT + r) * 4 + a] = (unsigned short)((a * 64 + idx) * 32);
        } else {
            float val = __shfl_sync(0xffffffffu, (idx < 32) ? v0 : v1, idx & 31);
            if (lane == 0) g_coef[d * RTOT + r] = (idx == 0) ? val : -val;
        }
    } else if (blk < NB_EXTRACT + NB_CT) {
        int id = (blk - NB_EXTRACT) * 256 + threadIdx.x;   // 131072
        int h  = id & 63;
        int n  = (id >> 6) & 15;
        int d  = (id >> 10) & 1;
        int kd = id >> 11;
        const float* C = d ? C2 : C1;
        g_Ct[id] = C[(h * 64 + kd) * 16 + n] * 0.25f;
    } else {
        int id = (blk - NB_EXTRACT - NB_CT) * 256 + threadIdx.x;
        if (id < 4096) {
            float s = 1.f / (1.f + expf(-A[id]));
            int a = id >> 10, t = id & 1023;
            float cur = 1.f;
            #pragma unroll
            for (int v = 0; v < VPOW; v++) {
                g_Apow[(a * VPOW + v) * 1024 + t] = cur;
                cur *= s;
            }
        } else if (id < 4096 + 2048) {
            int j = id - 4096;
            const float* B = (j < 1024) ? B1 : B2;
            g_Bsig[j] = 1.f / (1.f + expf(-B[j & 1023]));
        }
    }
}

// ---------------- 3. w[d][p][t], LDS.128 gathers, 1024 blocks ----------------
__global__ void k_w() {
    __shared__ float sA[4 * VPOW * 32];            // 32 KB Apow slice for t-chunk
    int tc = blockIdx.x, pc = blockIdx.y, d = blockIdx.z;
    int tid = threadIdx.x;
    for (int idx = tid; idx < 8192; idx += 256)
        sA[idx] = g_Apow[(idx >> 5) * 1024 + tc * 32 + (idx & 31)];
    __syncthreads();

    int warp = tid >> 5, lane = tid & 31;
    int pq = lane >> 3, tq = lane & 7;
    int t4 = tq * 4;
    int tg = tc * 32 + t4;
    float4 b0 = *(const float4*)&g_Bsig[tg];
    float4 b1 = *(const float4*)&g_Bsig[1024 + tg];
    const ushort4* offp = (const ushort4*)g_off16;

    #pragma unroll 1
    for (int pass = 0; pass < 2; pass++) {
        int p = pc * 64 + pass * 32 + warp * 4 + pq;
        int rb = d * RTOT + p * 16;
        float4 acc = make_float4(0.f, 0.f, 0.f, 0.f);
        #pragma unroll
        for (int r2 = 0; r2 < R2; r2++) {
            ushort4 o = offp[rb + r2];
            float  cf = g_coef[rb + r2];
            float4 v0 = *(const float4*)&sA[o.x + t4];
            float4 v1 = *(const float4*)&sA[o.y + t4];
            float4 v2 = *(const float4*)&sA[o.z + t4];
            float4 v3 = *(const float4*)&sA[o.w + t4];
            float s = fabsf(cf);
            float4 bb = (cf > 0.f) ? b0 : b1;
            acc.x = fmaf(v0.x * v1.x * v2.x * v3.x * s, bb.x, acc.x);
            acc.y = fmaf(v0.y * v1.y * v2.y * v3.y * s, bb.y, acc.y);
            acc.z = fmaf(v0.z * v1.z * v2.z * v3.z * s, bb.z, acc.z);
            acc.w = fmaf(v0.w * v1.w * v2.w * v3.w * s, bb.w, acc.w);
        }
        *(float4*)&g_w[(d * 1024 + p) * 1024 + tg] = acc;
    }
}

// ---------------- 4. kk = W x C, smem GEMM -----------------------------------
__global__ void k_kk() {
    __shared__ float Csm[32 * 64];                 // [c][h], c=(d*16+n)
    __shared__ float Wsm[32 * 66];                 // [c][p_l], padded
    int kd = blockIdx.x, pc = blockIdx.y, tid = threadIdx.x;
    int p0 = pc * 64;
    const float* ct = g_Ct + kd * 2048;
    for (int idx = tid; idx < 2048; idx += 256)
        Csm[idx] = ct[idx];
    for (int idx = tid; idx < 2048; idx += 256) {
        int p_l = idx >> 5, c = idx & 31;
        int d = c >> 4, n = c & 15;
        Wsm[c * 66 + p_l] = g_w[(d * 1024 + p0 + p_l) * 1024 + kd * 16 + n];
    }
    __syncthreads();
    int pg = tid >> 3, hg = tid & 7;
    float acc[2][8];
    #pragma unroll
    for (int pi = 0; pi < 2; pi++)
        #pragma unroll
        for (int hi = 0; hi < 8; hi++) acc[pi][hi] = 0.f;
    #pragma unroll
    for (int c = 0; c < 32; c++) {
        float w0 = Wsm[c * 66 + pg * 2];
        float w1 = Wsm[c * 66 + pg * 2 + 1];
        float4 c0 = *(const float4*)&Csm[c * 64 + hg * 8];
        float4 c1 = *(const float4*)&Csm[c * 64 + hg * 8 + 4];
        float cc[8] = {c0.x, c0.y, c0.z, c0.w, c1.x, c1.y, c1.z, c1.w};
        #pragma unroll
        for (int hi = 0; hi < 8; hi++) {
            acc[0][hi] = fmaf(w0, cc[hi], acc[0][hi]);
            acc[1][hi] = fmaf(w1, cc[hi], acc[1][hi]);
        }
    }
    #pragma unroll
    for (int pi = 0; pi < 2; pi++) {
        int p = p0 + pg * 2 + pi;
        float4* dst = (float4*)&g_kk[p * 4096 + kd * 64 + hg * 8];
        dst[0] = make_float4(acc[pi][0], acc[pi][1], acc[pi][2], acc[pi][3]);
        dst[1] = make_float4(acc[pi][4], acc[pi][5], acc[pi][6], acc[pi][7]);
    }
}

// ---------------- 5. flips + boundary scaling, fully float4-vectorized -------
__device__ __forceinline__ float bfactor(int a, int b) {
    float f = 1.f;
    if (a == 0) f *= 2.f;
    if (b == 0) f *= 2.f;
    if (a == 0 && b == 0) f *= 0.25f;
    return f;
}

__global__ void k_ksum() {
    __shared__ float sh[4][1024];
    int pi = blockIdx.x, pj = blockIdx.y, tid = threadIdx.x;
    int rows[4] = { pi * 32 + pj, (31 - pi) * 32 + pj,
                    pi * 32 + (31 - pj), (31 - pi) * 32 + (31 - pj) };
    // fill: one LDG.128 + STS.128 per (dir, thread) — 4 KB/dir across 256 thr
    #pragma unroll
    for (int dir = 0; dir < 4; dir++) {
        float4 v = *(const float4*)(g_kk + (size_t)rows[dir] * 4096 + dir * 1024 + tid * 4);
        *(float4*)&sh[dir][tid * 4] = v;
    }
    __syncthreads();
    float f0 = bfactor(pi, pj), f1 = bfactor(31 - pi, pj);
    float f2 = bfactor(pi, 31 - pj), f3 = bfactor(31 - pi, 31 - pj);
    // output: e-group of 4 shares h (e0 = tid*4, s = e&15 spans s0..s0+3)
    int e0 = tid * 4;
    int h  = e0 >> 4;
    int s0 = e0 & 15;
    float4 r;
    float* rp = (float*)&r;
    #pragma unroll
    for (int c = 0; c < 4; c++) {
        int o = (s0 + c) * 64 + h;
        rp[c] = f0 * sh[0][o] + f1 * sh[1][o] + f2 * sh[2][o] + f3 * sh[3][o];
    }
    *(float4*)(g_ksum + (size_t)(pi * 32 + pj) * 1024 + e0) = r;
}

// ---------------- 6. triangular conv (R8 measured-best, at fp32 roofline) ----
__global__ void __launch_bounds__(128, 3)
k_conv(const float* __restrict__ x, const float* __restrict__ omega,
       float* __restrict__ out) {
    int e  = blockIdx.x * 128 + threadIdx.x;
    int i  = 31 - (int)blockIdx.y;                 // heavy blocks launch first
    int b0 = blockIdx.z * 2;

    ull acc[32];                                   // lanes = (b0, b0+1)
    #pragma unroll
    for (int j = 0; j < 32; j++) acc[j] = 0ull;
    ull xr[32];

    const float* xa = x + b0 * 1024 + e;           // advances one grid-row per u
    const float* ka = g_ksum + (size_t)(i * 32) * 1024 + e;

    #pragma unroll 1
    for (int u = 0; u <= i; u++) {
        #pragma unroll
        for (int j = 0; j < 32; j++)
            xr[j] = pk2(xa[j * 8192], xa[j * 8192 + 1024]);
        #pragma unroll
        for (int qc = 0; qc < 4; qc++) {
            ull k2[8];
            #pragma unroll
            for (int t = 0; t < 8; t++) {
                float kv = ka[(qc * 8 + t) * 1024];
                k2[t] = pk2(kv, kv);
            }
            #pragma unroll
            for (int j = qc * 8; j < 32; j++) {
                int qmax = (j < qc * 8 + 7) ? j : (qc * 8 + 7);
                #pragma unroll
                for (int q = qc * 8; q <= qmax; q++)
                    fma2(acc[j], k2[q - qc * 8], xr[j - q]);
            }
        }
        xa += 32 * 8192;
        ka -= 32 * 1024;
    }

    // xr holds x grid-row i (last u) -> fused residual
    float om = omega[e];
    ull omp = pk2(om, om);
    float* oa = out + (size_t)((i * 32) * 8 + b0) * 1024 + e;
    #pragma unroll
    for (int j = 0; j < 32; j++) {
        fma2(acc[j], omp, xr[j]);
        float2 v = upk2(acc[j]);
        oa[j * 8192]        = v.x;
        oa[j * 8192 + 1024] = v.y;
    }
}

// ---------------- launch -----------------------------------------------------
extern "C" void kernel_launch(void* const* d_in, const int* in_sizes, int n_in,
                              void* d_out, int out_size) {
    const float* x   = (const float*)d_in[0];
    const float* A   = (const float*)d_in[1];
    const float* B1  = (const float*)d_in[2];
    const float* B2  = (const float*)d_in[3];
    const float* C1  = (const float*)d_in[4];
    const float* C2  = (const float*)d_in[5];
    const float* om  = (const float*)d_in[6];
    const float* OM  = (const float*)d_in[7];
    float* out = (float*)d_out;

    k_init<<<NB_EXTRACT + NB_CT + NB_SETUP, 256>>>(A, B1, B2, C1, C2, OM);
    k_w<<<dim3(32, 16, 2), 256>>>();
    k_kk<<<dim3(64, 16), 256>>>();
    k_ksum<<<dim3(32, 32), 256>>>();
    k_conv<<<dim3(8, 32, 4), 128>>>(x, om, out);
}